// round 14
// baseline (speedup 1.0000x reference)
#include <cuda_runtime.h>
#include <cuda_fp16.h>
#include <math.h>
#include <stdint.h>

#define NND    8192
#define IN_F   512
#define F      64
#define ALPHA  0.2f

#define JSPLIT 4
#define KRANGE (NND / JSPLIT)      // 2048 j per CTA
#define KSTEPS (KRANGE / 16)       // 128
#define NJBLK  (NND / 16)          // 512

typedef unsigned long long ull;
typedef unsigned int u32;

// ---------------- device scratch ----------------
__device__ float  g_h[NND * F];                    // 2 MB
__device__ float  g_e1[NND];
__device__ float  g_e2[NND];
__device__ float  g_maxe2;
__device__ float2 g_fBD[NND];                      // per-j (Q_j, D_j)
__device__ uint4  g_hB[NJBLK * 8 * 32];            // B frags {b0h,b1h,b0l,b1l} fp16
__device__ float  g_part[(long)JSPLIT * NND * F];  // 8 MB partials
__device__ float  g_zpart[JSPLIT * NND];

// ---------------- helpers ----------------
__device__ __forceinline__ ull pack2(float x, float y) {
    ull r; asm("mov.b64 %0, {%1, %2};" : "=l"(r) : "f"(x), "f"(y)); return r;
}
__device__ __forceinline__ void ffma2(ull &d, ull a, ull b) {
    asm("fma.rn.f32x2 %0, %1, %2, %3;" : "=l"(d) : "l"(a), "l"(b), "l"(d));
}
__device__ __forceinline__ float2 unpack2(ull v) {
    float2 r; asm("mov.b64 {%0, %1}, %2;" : "=f"(r.x), "=f"(r.y) : "l"(v)); return r;
}
// pack fp16x2: lo -> low half (even k), hi -> high half (odd k)
__device__ __forceinline__ u32 cvt2h(float lo, float hi) {
    u32 r; asm("cvt.rn.f16x2.f32 %0, %1, %2;" : "=r"(r) : "f"(hi), "f"(lo)); return r;
}
__device__ __forceinline__ float h2f_lo(u32 p) {
    __half h = __ushort_as_half((unsigned short)(p & 0xFFFFu));
    return __half2float(h);
}
__device__ __forceinline__ float h2f_hi(u32 p) {
    __half h = __ushort_as_half((unsigned short)(p >> 16));
    return __half2float(h);
}

// m16n8k16 fp16 MMA, f32 accumulate (base PTX, valid for compute_103)
__device__ __forceinline__ void mma_f16(float* d,
                                        u32 a0, u32 a1, u32 a2, u32 a3,
                                        u32 b0, u32 b1) {
    asm volatile(
        "mma.sync.aligned.m16n8k16.row.col.f32.f16.f16.f32 "
        "{%0,%1,%2,%3}, {%4,%5,%6,%7}, {%8,%9}, {%0,%1,%2,%3};"
        : "+f"(d[0]), "+f"(d[1]), "+f"(d[2]), "+f"(d[3])
        : "r"(a0), "r"(a1), "r"(a2), "r"(a3), "r"(b0), "r"(b1));
}

// ---------------- kernel 1: h = x @ W (fp32 f32x2 SIMT) ----------------
__global__ __launch_bounds__(256) void gemm_h_kernel(const float* __restrict__ x,
                                                     const float* __restrict__ W) {
    __shared__ float xs[64 * 68];
    __shared__ float wsm[64 * 64];

    const int tid = threadIdx.x;
    const int i0  = blockIdx.x * 64;
    const int tf  = tid & 15;
    const int tg  = tid >> 4;

    ull acc[4][2];
#pragma unroll
    for (int r = 0; r < 4; r++) { acc[r][0] = 0ull; acc[r][1] = 0ull; }

    for (int kt = 0; kt < IN_F; kt += 64) {
#pragma unroll
        for (int q = tid; q < 1024; q += 256) {
            int row = q >> 4, c4 = q & 15;
            float4 v = *(const float4*)(x + (long)(i0 + row) * IN_F + kt + c4 * 4);
            *(float4*)(xs + row * 68 + c4 * 4) = v;
        }
#pragma unroll
        for (int q = tid; q < 1024; q += 256) {
            float4 v = *(const float4*)(W + (long)kt * F + q * 4);
            *(float4*)(wsm + q * 4) = v;
        }
        __syncthreads();
#pragma unroll 8
        for (int kk = 0; kk < 64; kk++) {
            ulonglong2 wp = *(const ulonglong2*)(wsm + kk * 64 + tf * 4);
#pragma unroll
            for (int r = 0; r < 4; r++) {
                float xv = xs[(tg * 4 + r) * 68 + kk];
                ull x2 = pack2(xv, xv);
                ffma2(acc[r][0], x2, wp.x);
                ffma2(acc[r][1], x2, wp.y);
            }
        }
        __syncthreads();
    }
#pragma unroll
    for (int r = 0; r < 4; r++) {
        float2 lo = unpack2(acc[r][0]);
        float2 hi = unpack2(acc[r][1]);
        *(float4*)(g_h + (long)(i0 + tg * 4 + r) * F + tf * 4) =
            make_float4(lo.x, lo.y, hi.x, hi.y);
    }
}

// ---------------- kernel 2: e1 = h@a1, e2 = h@a2 (warp per row) ----------------
__global__ __launch_bounds__(256) void e12_kernel(const float* __restrict__ a) {
    const int tid  = threadIdx.x;
    const int lane = tid & 31;
    const int row  = blockIdx.x * 8 + (tid >> 5);

    float h0 = g_h[row * F + 2 * lane];
    float h1 = g_h[row * F + 2 * lane + 1];
    float p1 = h0 * a[2 * lane]      + h1 * a[2 * lane + 1];
    float p2 = h0 * a[64 + 2 * lane] + h1 * a[64 + 2 * lane + 1];
#pragma unroll
    for (int off = 16; off > 0; off >>= 1) {
        p1 += __shfl_xor_sync(0xffffffffu, p1, off);
        p2 += __shfl_xor_sync(0xffffffffu, p2, off);
    }
    if (lane == 0) { g_e1[row] = p1; g_e2[row] = p2; }
}

// ---- kernel 3: prep = max(e2) (redundant/block) + fbd (blocks 0-31) + hfrag
__global__ __launch_bounds__(256) void prep_kernel() {
    __shared__ float sm[8];
    const int tid = threadIdx.x;

    // redundant global max of e2 (L2-hot)
    float v = -3.4e38f;
#pragma unroll
    for (int k = 0; k < NND / 256; k++) v = fmaxf(v, g_e2[k * 256 + tid]);
#pragma unroll
    for (int off = 16; off > 0; off >>= 1)
        v = fmaxf(v, __shfl_xor_sync(0xffffffffu, v, off));
    if ((tid & 31) == 0) sm[tid >> 5] = v;
    __syncthreads();
    const float mx = fmaxf(fmaxf(fmaxf(sm[0], sm[1]), fmaxf(sm[2], sm[3])),
                           fmaxf(fmaxf(sm[4], sm[5]), fmaxf(sm[6], sm[7])));

    if (blockIdx.x == 0 && tid == 0) g_maxe2 = mx;

    // fbd: blocks 0..31 cover all 8192 j
    if (blockIdx.x < 32) {
        const int j = blockIdx.x * 256 + tid;
        const float d = g_e2[j] - mx;
        g_fBD[j] = make_float2(__expf(d), __expf(ALPHA * d));
    }

    // hfrag: idx = jblk*256 + nb*32 + lane  (split-fp16 B fragments)
    const int idx  = blockIdx.x * 256 + tid;
    const int lane = idx & 31;
    const int nb   = (idx >> 5) & 7;
    const int jblk = idx >> 8;
    const int q    = lane & 3;
    const int nr   = lane >> 2;
    const int n    = nb * 8 + nr;
    const int j0   = jblk * 16 + 4 * q;

    float v0 = g_h[(long)(j0 + 0) * F + n];
    float v1 = g_h[(long)(j0 + 1) * F + n];
    float v2 = g_h[(long)(j0 + 2) * F + n];
    float v3 = g_h[(long)(j0 + 3) * F + n];

    u32 b0h = cvt2h(v0, v1);
    u32 b1h = cvt2h(v2, v3);
    u32 b0l = cvt2h(v0 - h2f_lo(b0h), v1 - h2f_hi(b0h));
    u32 b1l = cvt2h(v2 - h2f_lo(b1h), v3 - h2f_hi(b1h));
    g_hB[idx] = make_uint4(b0h, b1h, b0l, b1l);
}

// ---------------- kernel 4: HMMA masked-softmax aggregate ----------------
// 256 CTAs (64 row-blocks x 4 j-splits), 256 threads, no smem/barriers.
// THIS ROUND: register diet -> 3 CTAs/SM. __launch_bounds__(256,3) caps regs
// at 85; B loads split into 2 groups of 4 to shrink live range. Everything
// else identical to the measured 133.9us configuration.
__global__ __launch_bounds__(256, 3) void hmma_agg_kernel(const int* __restrict__ adj) {
    const int tid  = threadIdx.x;
    const int wid  = tid >> 5;
    const int lane = tid & 31;
    const int q    = lane & 3;
    const int r0   = lane >> 2;
    const int s    = blockIdx.x & (JSPLIT - 1);
    const int i0   = (blockIdx.x >> 2) * 128;
    const int jbase = s * KRANGE;

    const int row0 = i0 + wid * 16 + r0;
    const int row1 = row0 + 8;

    // per-row softmax constants
    const float mx = g_maxe2;
    float t0 = g_e1[row0] + mx, t1 = g_e1[row1] + mx;
    float m0 = fmaxf(t0, ALPHA * t0), m1 = fmaxf(t1, ALPHA * t1);
    const float P0 = __expf(t0 - m0), C0 = __expf(ALPHA * t0 - m0);
    const float P1 = __expf(t1 - m1), C1 = __expf(ALPHA * t1 - m1);

    const int4* a0p = (const int4*)(adj + (long)row0 * NND + jbase) + q;
    const int4* a1p = (const int4*)(adj + (long)row1 * NND + jbase) + q;
    const uint4* bbase = g_hB + ((long)(jbase >> 4)) * 256 + lane;

    float acc[8][4];
#pragma unroll
    for (int nb = 0; nb < 8; nb++)
#pragma unroll
        for (int c = 0; c < 4; c++) acc[nb][c] = 0.0f;
    float z0 = 0.0f, z1 = 0.0f;

    int4 av0 = __ldcs(a0p);
    int4 av1 = __ldcs(a1p);

    for (int t = 0; t < KSTEPS; t++) {
        const int4 c0 = av0, c1 = av1;
        if (t + 1 < KSTEPS) {                 // prefetch next kstep's adj
            av0 = __ldcs(a0p + (t + 1) * 4);
            av1 = __ldcs(a1p + (t + 1) * 4);
        }

        const int jq = jbase + t * 16 + 4 * q;
        const float4 f01 = *(const float4*)(g_fBD + jq);      // (Q0,D0,Q1,D1)
        const float4 f23 = *(const float4*)(g_fBD + jq + 2);  // (Q2,D2,Q3,D3)

        float w00 = c0.x ? fmaxf(P0 * f01.x, C0 * f01.y) : 0.0f;
        float w01 = c0.y ? fmaxf(P0 * f01.z, C0 * f01.w) : 0.0f;
        float w02 = c0.z ? fmaxf(P0 * f23.x, C0 * f23.y) : 0.0f;
        float w03 = c0.w ? fmaxf(P0 * f23.z, C0 * f23.w) : 0.0f;
        float w10 = c1.x ? fmaxf(P1 * f01.x, C1 * f01.y) : 0.0f;
        float w11 = c1.y ? fmaxf(P1 * f01.z, C1 * f01.w) : 0.0f;
        float w12 = c1.z ? fmaxf(P1 * f23.x, C1 * f23.y) : 0.0f;
        float w13 = c1.w ? fmaxf(P1 * f23.z, C1 * f23.w) : 0.0f;

        z0 += (w00 + w01) + (w02 + w03);
        z1 += (w10 + w11) + (w12 + w13);

        // A fragments (fp16): a0=(r0,klo) a1=(r1,klo) a2=(r0,khi) a3=(r1,khi)
        u32 a0 = cvt2h(w00, w01), a1 = cvt2h(w10, w11);
        u32 a2 = cvt2h(w02, w03), a3 = cvt2h(w12, w13);

        const uint4* bb = bbase + (long)t * 256;
        // two groups of 4 B-loads: live B regs 16 instead of 32
#pragma unroll
        for (int g = 0; g < 2; g++) {
            uint4 b0 = __ldg(bb + (g * 4 + 0) * 32);
            uint4 b1 = __ldg(bb + (g * 4 + 1) * 32);
            uint4 b2 = __ldg(bb + (g * 4 + 2) * 32);
            uint4 b3 = __ldg(bb + (g * 4 + 3) * 32);
            mma_f16(acc[g * 4 + 0], a0, a1, a2, a3, b0.x, b0.y);
            mma_f16(acc[g * 4 + 0], a0, a1, a2, a3, b0.z, b0.w);
            mma_f16(acc[g * 4 + 1], a0, a1, a2, a3, b1.x, b1.y);
            mma_f16(acc[g * 4 + 1], a0, a1, a2, a3, b1.z, b1.w);
            mma_f16(acc[g * 4 + 2], a0, a1, a2, a3, b2.x, b2.y);
            mma_f16(acc[g * 4 + 2], a0, a1, a2, a3, b2.z, b2.w);
            mma_f16(acc[g * 4 + 3], a0, a1, a2, a3, b3.x, b3.y);
            mma_f16(acc[g * 4 + 3], a0, a1, a2, a3, b3.z, b3.w);
        }
    }

    // Z reduce across q (lanes sharing r0)
    z0 += __shfl_xor_sync(0xffffffffu, z0, 1);
    z0 += __shfl_xor_sync(0xffffffffu, z0, 2);
    z1 += __shfl_xor_sync(0xffffffffu, z1, 1);
    z1 += __shfl_xor_sync(0xffffffffu, z1, 2);
    if (q == 0) {
        g_zpart[s * NND + row0] = z0;
        g_zpart[s * NND + row1] = z1;
    }

    // write D partials: d0,d1 -> row0 cols nb*8+2q..+1 ; d2,d3 -> row1
    float* p0 = g_part + ((long)s * NND + row0) * F + 2 * q;
    float* p1 = g_part + ((long)s * NND + row1) * F + 2 * q;
#pragma unroll
    for (int nb = 0; nb < 8; nb++) {
        *(float2*)(p0 + nb * 8) = make_float2(acc[nb][0], acc[nb][1]);
        *(float2*)(p1 + nb * 8) = make_float2(acc[nb][2], acc[nb][3]);
    }
}

// ---------------- kernel 5: combine splits, normalize, ELU (float4) --------
__global__ __launch_bounds__(256) void combine_kernel(float* __restrict__ out) {
    const int t4 = blockIdx.x * 256 + threadIdx.x;   // 0 .. N*F/4-1
    const int i  = t4 >> 4;                          // 16 float4 per row
    float4 acc = make_float4(0.f, 0.f, 0.f, 0.f);
    float  z   = 0.0f;
#pragma unroll
    for (int s = 0; s < JSPLIT; s++) {
        float4 p = __ldcs((const float4*)g_part + (long)s * (NND * F / 4) + t4);
        acc.x += p.x; acc.y += p.y; acc.z += p.z; acc.w += p.w;
        z     += g_zpart[s * NND + i];
    }
    const float zi = 1.0f / z;
    float o0 = acc.x * zi, o1 = acc.y * zi, o2 = acc.z * zi, o3 = acc.w * zi;
    float4 r;
    r.x = (o0 > 0.0f) ? o0 : expm1f(o0);
    r.y = (o1 > 0.0f) ? o1 : expm1f(o1);
    r.z = (o2 > 0.0f) ? o2 : expm1f(o2);
    r.w = (o3 > 0.0f) ? o3 : expm1f(o3);
    *((float4*)out + t4) = r;
}

// ---------------- launch ----------------
extern "C" void kernel_launch(void* const* d_in, const int* in_sizes, int n_in,
                              void* d_out, int out_size) {
    const float* x   = (const float*)d_in[0];
    const int*   adj = (const int*)  d_in[1];
    const float* W   = (const float*)d_in[2];
    const float* a   = (const float*)d_in[3];
    float* out = (float*)d_out;

    gemm_h_kernel<<<NND / 64, 256>>>(x, W);
    e12_kernel<<<NND / 8, 256>>>(a);
    prep_kernel<<<NJBLK, 256>>>();
    hmma_agg_kernel<<<(NND / 128) * JSPLIT, 256>>>(adj);   // launch index 3
    combine_kernel<<<(NND * F) / 1024, 256>>>(out);
}

// round 15
// speedup vs baseline: 1.9030x; 1.9030x over previous
#include <cuda_runtime.h>
#include <cuda_fp16.h>
#include <math.h>
#include <stdint.h>

#define NND    8192
#define IN_F   512
#define F      64
#define ALPHA  0.2f

#define JSPLIT 8
#define KRANGE (NND / JSPLIT)      // 1024 j per CTA
#define KSTEPS (KRANGE / 16)       // 64
#define NJBLK  (NND / 16)          // 512

typedef unsigned long long ull;
typedef unsigned int u32;

// ---------------- device scratch ----------------
__device__ float  g_h[NND * F];                    // 2 MB
__device__ float  g_e1[NND];
__device__ float  g_e2[NND];
__device__ float  g_maxe2;
__device__ float2 g_fBD[NND];                      // per-j (Q_j, D_j)
__device__ uint4  g_hB[NJBLK * 8 * 32];            // B frags {b0h,b1h,b0l,b1l} fp16
__device__ float  g_part[(long)JSPLIT * NND * F];  // 16 MB partials
__device__ float  g_zpart[JSPLIT * NND];

// ---------------- helpers ----------------
__device__ __forceinline__ ull pack2(float x, float y) {
    ull r; asm("mov.b64 %0, {%1, %2};" : "=l"(r) : "f"(x), "f"(y)); return r;
}
__device__ __forceinline__ void ffma2(ull &d, ull a, ull b) {
    asm("fma.rn.f32x2 %0, %1, %2, %3;" : "=l"(d) : "l"(a), "l"(b), "l"(d));
}
__device__ __forceinline__ float2 unpack2(ull v) {
    float2 r; asm("mov.b64 {%0, %1}, %2;" : "=f"(r.x), "=f"(r.y) : "l"(v)); return r;
}
// pack fp16x2: lo -> low half (even k), hi -> high half (odd k)
__device__ __forceinline__ u32 cvt2h(float lo, float hi) {
    u32 r; asm("cvt.rn.f16x2.f32 %0, %1, %2;" : "=r"(r) : "f"(hi), "f"(lo)); return r;
}
__device__ __forceinline__ float h2f_lo(u32 p) {
    __half h = __ushort_as_half((unsigned short)(p & 0xFFFFu));
    return __half2float(h);
}
__device__ __forceinline__ float h2f_hi(u32 p) {
    __half h = __ushort_as_half((unsigned short)(p >> 16));
    return __half2float(h);
}

// m16n8k16 fp16 MMA, f32 accumulate (base PTX, valid for compute_103)
__device__ __forceinline__ void mma_f16(float* d,
                                        u32 a0, u32 a1, u32 a2, u32 a3,
                                        u32 b0, u32 b1) {
    asm volatile(
        "mma.sync.aligned.m16n8k16.row.col.f32.f16.f16.f32 "
        "{%0,%1,%2,%3}, {%4,%5,%6,%7}, {%8,%9}, {%0,%1,%2,%3};"
        : "+f"(d[0]), "+f"(d[1]), "+f"(d[2]), "+f"(d[3])
        : "r"(a0), "r"(a1), "r"(a2), "r"(a3), "r"(b0), "r"(b1));
}

// ---------------- kernel 1: h = x @ W (fp32 f32x2 SIMT) ----------------
__global__ __launch_bounds__(256) void gemm_h_kernel(const float* __restrict__ x,
                                                     const float* __restrict__ W) {
    __shared__ float xs[64 * 68];
    __shared__ float wsm[64 * 64];

    const int tid = threadIdx.x;
    const int i0  = blockIdx.x * 64;
    const int tf  = tid & 15;
    const int tg  = tid >> 4;

    ull acc[4][2];
#pragma unroll
    for (int r = 0; r < 4; r++) { acc[r][0] = 0ull; acc[r][1] = 0ull; }

    for (int kt = 0; kt < IN_F; kt += 64) {
#pragma unroll
        for (int q = tid; q < 1024; q += 256) {
            int row = q >> 4, c4 = q & 15;
            float4 v = *(const float4*)(x + (long)(i0 + row) * IN_F + kt + c4 * 4);
            *(float4*)(xs + row * 68 + c4 * 4) = v;
        }
#pragma unroll
        for (int q = tid; q < 1024; q += 256) {
            float4 v = *(const float4*)(W + (long)kt * F + q * 4);
            *(float4*)(wsm + q * 4) = v;
        }
        __syncthreads();
#pragma unroll 8
        for (int kk = 0; kk < 64; kk++) {
            ulonglong2 wp = *(const ulonglong2*)(wsm + kk * 64 + tf * 4);
#pragma unroll
            for (int r = 0; r < 4; r++) {
                float xv = xs[(tg * 4 + r) * 68 + kk];
                ull x2 = pack2(xv, xv);
                ffma2(acc[r][0], x2, wp.x);
                ffma2(acc[r][1], x2, wp.y);
            }
        }
        __syncthreads();
    }
#pragma unroll
    for (int r = 0; r < 4; r++) {
        float2 lo = unpack2(acc[r][0]);
        float2 hi = unpack2(acc[r][1]);
        *(float4*)(g_h + (long)(i0 + tg * 4 + r) * F + tf * 4) =
            make_float4(lo.x, lo.y, hi.x, hi.y);
    }
}

// ---------------- kernel 2: e1 = h@a1, e2 = h@a2 (warp per row) ----------------
__global__ __launch_bounds__(256) void e12_kernel(const float* __restrict__ a) {
    const int tid  = threadIdx.x;
    const int lane = tid & 31;
    const int row  = blockIdx.x * 8 + (tid >> 5);

    float h0 = g_h[row * F + 2 * lane];
    float h1 = g_h[row * F + 2 * lane + 1];
    float p1 = h0 * a[2 * lane]      + h1 * a[2 * lane + 1];
    float p2 = h0 * a[64 + 2 * lane] + h1 * a[64 + 2 * lane + 1];
#pragma unroll
    for (int off = 16; off > 0; off >>= 1) {
        p1 += __shfl_xor_sync(0xffffffffu, p1, off);
        p2 += __shfl_xor_sync(0xffffffffu, p2, off);
    }
    if (lane == 0) { g_e1[row] = p1; g_e2[row] = p2; }
}

// ---- kernel 3: prep = max(e2) (redundant/block) + fbd (blocks 0-31) + hfrag
__global__ __launch_bounds__(256) void prep_kernel() {
    __shared__ float sm[8];
    const int tid = threadIdx.x;

    // redundant global max of e2 (L2-hot)
    float v = -3.4e38f;
#pragma unroll
    for (int k = 0; k < NND / 256; k++) v = fmaxf(v, g_e2[k * 256 + tid]);
#pragma unroll
    for (int off = 16; off > 0; off >>= 1)
        v = fmaxf(v, __shfl_xor_sync(0xffffffffu, v, off));
    if ((tid & 31) == 0) sm[tid >> 5] = v;
    __syncthreads();
    const float mx = fmaxf(fmaxf(fmaxf(sm[0], sm[1]), fmaxf(sm[2], sm[3])),
                           fmaxf(fmaxf(sm[4], sm[5]), fmaxf(sm[6], sm[7])));

    if (blockIdx.x == 0 && tid == 0) g_maxe2 = mx;

    // fbd: blocks 0..31 cover all 8192 j
    if (blockIdx.x < 32) {
        const int j = blockIdx.x * 256 + tid;
        const float d = g_e2[j] - mx;
        g_fBD[j] = make_float2(__expf(d), __expf(ALPHA * d));
    }

    // hfrag: idx = jblk*256 + nb*32 + lane  (split-fp16 B fragments)
    const int idx  = blockIdx.x * 256 + tid;
    const int lane = idx & 31;
    const int nb   = (idx >> 5) & 7;
    const int jblk = idx >> 8;
    const int q    = lane & 3;
    const int nr   = lane >> 2;
    const int n    = nb * 8 + nr;
    const int j0   = jblk * 16 + 4 * q;

    float v0 = g_h[(long)(j0 + 0) * F + n];
    float v1 = g_h[(long)(j0 + 1) * F + n];
    float v2 = g_h[(long)(j0 + 2) * F + n];
    float v3 = g_h[(long)(j0 + 3) * F + n];

    u32 b0h = cvt2h(v0, v1);
    u32 b1h = cvt2h(v2, v3);
    u32 b0l = cvt2h(v0 - h2f_lo(b0h), v1 - h2f_hi(b0h));
    u32 b1l = cvt2h(v2 - h2f_lo(b1h), v3 - h2f_hi(b1h));
    g_hB[idx] = make_uint4(b0h, b1h, b0l, b1l);
}

// ---------------- kernel 4: HMMA masked-softmax aggregate ----------------
// 512 CTAs (64 row-blocks x 8 j-splits), 256 threads, no smem/barriers.
// R13 body (measured best per-SM form), JSPLIT doubled for grid balance:
// 512 CTAs / 152 SMs with 2-resident + work stealing -> ~6% tail vs 19%.
__global__ __launch_bounds__(256, 2) void hmma_agg_kernel(const int* __restrict__ adj) {
    const int tid  = threadIdx.x;
    const int wid  = tid >> 5;
    const int lane = tid & 31;
    const int q    = lane & 3;
    const int r0   = lane >> 2;
    const int s    = blockIdx.x & (JSPLIT - 1);
    const int i0   = (blockIdx.x >> 3) * 128;
    const int jbase = s * KRANGE;

    const int row0 = i0 + wid * 16 + r0;
    const int row1 = row0 + 8;

    // per-row softmax constants
    const float mx = g_maxe2;
    float t0 = g_e1[row0] + mx, t1 = g_e1[row1] + mx;
    float m0 = fmaxf(t0, ALPHA * t0), m1 = fmaxf(t1, ALPHA * t1);
    const float P0 = __expf(t0 - m0), C0 = __expf(ALPHA * t0 - m0);
    const float P1 = __expf(t1 - m1), C1 = __expf(ALPHA * t1 - m1);

    const int4* a0p = (const int4*)(adj + (long)row0 * NND + jbase) + q;
    const int4* a1p = (const int4*)(adj + (long)row1 * NND + jbase) + q;
    const uint4* bbase = g_hB + ((long)(jbase >> 4)) * 256 + lane;

    float acc[8][4];
#pragma unroll
    for (int nb = 0; nb < 8; nb++)
#pragma unroll
        for (int c = 0; c < 4; c++) acc[nb][c] = 0.0f;
    float z0 = 0.0f, z1 = 0.0f;

    int4 av0 = __ldcs(a0p);
    int4 av1 = __ldcs(a1p);

    for (int t = 0; t < KSTEPS; t++) {
        const int4 c0 = av0, c1 = av1;
        if (t + 1 < KSTEPS) {                 // prefetch next kstep's adj
            av0 = __ldcs(a0p + (t + 1) * 4);
            av1 = __ldcs(a1p + (t + 1) * 4);
        }

        const int jq = jbase + t * 16 + 4 * q;
        const float4 f01 = *(const float4*)(g_fBD + jq);      // (Q0,D0,Q1,D1)
        const float4 f23 = *(const float4*)(g_fBD + jq + 2);  // (Q2,D2,Q3,D3)

        float w00 = c0.x ? fmaxf(P0 * f01.x, C0 * f01.y) : 0.0f;
        float w01 = c0.y ? fmaxf(P0 * f01.z, C0 * f01.w) : 0.0f;
        float w02 = c0.z ? fmaxf(P0 * f23.x, C0 * f23.y) : 0.0f;
        float w03 = c0.w ? fmaxf(P0 * f23.z, C0 * f23.w) : 0.0f;
        float w10 = c1.x ? fmaxf(P1 * f01.x, C1 * f01.y) : 0.0f;
        float w11 = c1.y ? fmaxf(P1 * f01.z, C1 * f01.w) : 0.0f;
        float w12 = c1.z ? fmaxf(P1 * f23.x, C1 * f23.y) : 0.0f;
        float w13 = c1.w ? fmaxf(P1 * f23.z, C1 * f23.w) : 0.0f;

        z0 += (w00 + w01) + (w02 + w03);
        z1 += (w10 + w11) + (w12 + w13);

        // A fragments (fp16): a0=(r0,klo) a1=(r1,klo) a2=(r0,khi) a3=(r1,khi)
        u32 a0 = cvt2h(w00, w01), a1 = cvt2h(w10, w11);
        u32 a2 = cvt2h(w02, w03), a3 = cvt2h(w12, w13);

        const uint4* bb = bbase + (long)t * 256;
#pragma unroll
        for (int nb = 0; nb < 8; nb++) {
            uint4 b = __ldg(bb + nb * 32);
            mma_f16(acc[nb], a0, a1, a2, a3, b.x, b.y);  // w * h_hi
            mma_f16(acc[nb], a0, a1, a2, a3, b.z, b.w);  // w * h_lo
        }
    }

    // Z reduce across q (lanes sharing r0)
    z0 += __shfl_xor_sync(0xffffffffu, z0, 1);
    z0 += __shfl_xor_sync(0xffffffffu, z0, 2);
    z1 += __shfl_xor_sync(0xffffffffu, z1, 1);
    z1 += __shfl_xor_sync(0xffffffffu, z1, 2);
    if (q == 0) {
        g_zpart[s * NND + row0] = z0;
        g_zpart[s * NND + row1] = z1;
    }

    // write D partials: d0,d1 -> row0 cols nb*8+2q..+1 ; d2,d3 -> row1
    float* p0 = g_part + ((long)s * NND + row0) * F + 2 * q;
    float* p1 = g_part + ((long)s * NND + row1) * F + 2 * q;
#pragma unroll
    for (int nb = 0; nb < 8; nb++) {
        *(float2*)(p0 + nb * 8) = make_float2(acc[nb][0], acc[nb][1]);
        *(float2*)(p1 + nb * 8) = make_float2(acc[nb][2], acc[nb][3]);
    }
}

// ---------------- kernel 5: combine splits, normalize, ELU (float4) --------
__global__ __launch_bounds__(256) void combine_kernel(float* __restrict__ out) {
    const int t4 = blockIdx.x * 256 + threadIdx.x;   // 0 .. N*F/4-1
    const int i  = t4 >> 4;                          // 16 float4 per row
    float4 acc = make_float4(0.f, 0.f, 0.f, 0.f);
    float  z   = 0.0f;
#pragma unroll
    for (int s = 0; s < JSPLIT; s++) {
        float4 p = __ldcs((const float4*)g_part + (long)s * (NND * F / 4) + t4);
        acc.x += p.x; acc.y += p.y; acc.z += p.z; acc.w += p.w;
        z     += g_zpart[s * NND + i];
    }
    const float zi = 1.0f / z;
    float o0 = acc.x * zi, o1 = acc.y * zi, o2 = acc.z * zi, o3 = acc.w * zi;
    float4 r;
    r.x = (o0 > 0.0f) ? o0 : expm1f(o0);
    r.y = (o1 > 0.0f) ? o1 : expm1f(o1);
    r.z = (o2 > 0.0f) ? o2 : expm1f(o2);
    r.w = (o3 > 0.0f) ? o3 : expm1f(o3);
    *((float4*)out + t4) = r;
}

// ---------------- launch ----------------
extern "C" void kernel_launch(void* const* d_in, const int* in_sizes, int n_in,
                              void* d_out, int out_size) {
    const float* x   = (const float*)d_in[0];
    const int*   adj = (const int*)  d_in[1];
    const float* W   = (const float*)d_in[2];
    const float* a   = (const float*)d_in[3];
    float* out = (float*)d_out;

    gemm_h_kernel<<<NND / 64, 256>>>(x, W);
    e12_kernel<<<NND / 8, 256>>>(a);
    prep_kernel<<<NJBLK, 256>>>();
    hmma_agg_kernel<<<(NND / 128) * JSPLIT, 256>>>(adj);   // 512 CTAs
    combine_kernel<<<(NND * F) / 1024, 256>>>(out);
}

// round 16
// speedup vs baseline: 2.1680x; 1.1393x over previous
#include <cuda_runtime.h>
#include <cuda_fp16.h>
#include <math.h>
#include <stdint.h>

#define NND    8192
#define IN_F   512
#define F      64
#define ALPHA  0.2f

#define JSPLIT 8
#define KRANGE (NND / JSPLIT)      // 1024 j per CTA
#define KSTEPS (KRANGE / 16)       // 64
#define NJBLK  (NND / 16)          // 512

typedef unsigned long long ull;
typedef unsigned int u32;

// ---------------- device scratch ----------------
__device__ float  g_h[NND * F];                    // 2 MB
__device__ float  g_e1[NND];
__device__ float  g_e2[NND];
__device__ float  g_maxe2;
__device__ float2 g_fBD[NND];                      // per-j (Q_j, D_j)
__device__ uint2  g_hB2[NJBLK * 8 * 32];           // B frags {b0h,b1h} fp16, 1 MB
__device__ float  g_part[(long)JSPLIT * NND * F];  // 16 MB partials
__device__ float  g_zpart[JSPLIT * NND];

// ---------------- helpers ----------------
__device__ __forceinline__ ull pack2(float x, float y) {
    ull r; asm("mov.b64 %0, {%1, %2};" : "=l"(r) : "f"(x), "f"(y)); return r;
}
__device__ __forceinline__ void ffma2(ull &d, ull a, ull b) {
    asm("fma.rn.f32x2 %0, %1, %2, %3;" : "=l"(d) : "l"(a), "l"(b), "l"(d));
}
__device__ __forceinline__ float2 unpack2(ull v) {
    float2 r; asm("mov.b64 {%0, %1}, %2;" : "=f"(r.x), "=f"(r.y) : "l"(v)); return r;
}
// pack fp16x2: lo -> low half (even k), hi -> high half (odd k)
__device__ __forceinline__ u32 cvt2h(float lo, float hi) {
    u32 r; asm("cvt.rn.f16x2.f32 %0, %1, %2;" : "=r"(r) : "f"(hi), "f"(lo)); return r;
}

// m16n8k16 fp16 MMA, f32 accumulate (base PTX, valid for compute_103)
__device__ __forceinline__ void mma_f16(float* d,
                                        u32 a0, u32 a1, u32 a2, u32 a3,
                                        u32 b0, u32 b1) {
    asm volatile(
        "mma.sync.aligned.m16n8k16.row.col.f32.f16.f16.f32 "
        "{%0,%1,%2,%3}, {%4,%5,%6,%7}, {%8,%9}, {%0,%1,%2,%3};"
        : "+f"(d[0]), "+f"(d[1]), "+f"(d[2]), "+f"(d[3])
        : "r"(a0), "r"(a1), "r"(a2), "r"(a3), "r"(b0), "r"(b1));
}

// ---------------- kernel 1: h = x @ W (fp32 f32x2 SIMT) ----------------
__global__ __launch_bounds__(256) void gemm_h_kernel(const float* __restrict__ x,
                                                     const float* __restrict__ W) {
    __shared__ float xs[64 * 68];
    __shared__ float wsm[64 * 64];

    const int tid = threadIdx.x;
    const int i0  = blockIdx.x * 64;
    const int tf  = tid & 15;
    const int tg  = tid >> 4;

    ull acc[4][2];
#pragma unroll
    for (int r = 0; r < 4; r++) { acc[r][0] = 0ull; acc[r][1] = 0ull; }

    for (int kt = 0; kt < IN_F; kt += 64) {
#pragma unroll
        for (int q = tid; q < 1024; q += 256) {
            int row = q >> 4, c4 = q & 15;
            float4 v = *(const float4*)(x + (long)(i0 + row) * IN_F + kt + c4 * 4);
            *(float4*)(xs + row * 68 + c4 * 4) = v;
        }
#pragma unroll
        for (int q = tid; q < 1024; q += 256) {
            float4 v = *(const float4*)(W + (long)kt * F + q * 4);
            *(float4*)(wsm + q * 4) = v;
        }
        __syncthreads();
#pragma unroll 8
        for (int kk = 0; kk < 64; kk++) {
            ulonglong2 wp = *(const ulonglong2*)(wsm + kk * 64 + tf * 4);
#pragma unroll
            for (int r = 0; r < 4; r++) {
                float xv = xs[(tg * 4 + r) * 68 + kk];
                ull x2 = pack2(xv, xv);
                ffma2(acc[r][0], x2, wp.x);
                ffma2(acc[r][1], x2, wp.y);
            }
        }
        __syncthreads();
    }
#pragma unroll
    for (int r = 0; r < 4; r++) {
        float2 lo = unpack2(acc[r][0]);
        float2 hi = unpack2(acc[r][1]);
        *(float4*)(g_h + (long)(i0 + tg * 4 + r) * F + tf * 4) =
            make_float4(lo.x, lo.y, hi.x, hi.y);
    }
}

// ---------------- kernel 2: e1 = h@a1, e2 = h@a2 (warp per row) ----------------
__global__ __launch_bounds__(256) void e12_kernel(const float* __restrict__ a) {
    const int tid  = threadIdx.x;
    const int lane = tid & 31;
    const int row  = blockIdx.x * 8 + (tid >> 5);

    float h0 = g_h[row * F + 2 * lane];
    float h1 = g_h[row * F + 2 * lane + 1];
    float p1 = h0 * a[2 * lane]      + h1 * a[2 * lane + 1];
    float p2 = h0 * a[64 + 2 * lane] + h1 * a[64 + 2 * lane + 1];
#pragma unroll
    for (int off = 16; off > 0; off >>= 1) {
        p1 += __shfl_xor_sync(0xffffffffu, p1, off);
        p2 += __shfl_xor_sync(0xffffffffu, p2, off);
    }
    if (lane == 0) { g_e1[row] = p1; g_e2[row] = p2; }
}

// ---- kernel 3: prep = max(e2) (redundant/block) + fbd (blocks 0-31) + hfrag
__global__ __launch_bounds__(256) void prep_kernel() {
    __shared__ float sm[8];
    const int tid = threadIdx.x;

    // redundant global max of e2 (L2-hot)
    float v = -3.4e38f;
#pragma unroll
    for (int k = 0; k < NND / 256; k++) v = fmaxf(v, g_e2[k * 256 + tid]);
#pragma unroll
    for (int off = 16; off > 0; off >>= 1)
        v = fmaxf(v, __shfl_xor_sync(0xffffffffu, v, off));
    if ((tid & 31) == 0) sm[tid >> 5] = v;
    __syncthreads();
    const float mx = fmaxf(fmaxf(fmaxf(sm[0], sm[1]), fmaxf(sm[2], sm[3])),
                           fmaxf(fmaxf(sm[4], sm[5]), fmaxf(sm[6], sm[7])));

    if (blockIdx.x == 0 && tid == 0) g_maxe2 = mx;

    // fbd: blocks 0..31 cover all 8192 j
    if (blockIdx.x < 32) {
        const int j = blockIdx.x * 256 + tid;
        const float d = g_e2[j] - mx;
        g_fBD[j] = make_float2(__expf(d), __expf(ALPHA * d));
    }

    // hfrag: idx = jblk*256 + nb*32 + lane  (fp16 B fragments, no split)
    const int idx  = blockIdx.x * 256 + tid;
    const int lane = idx & 31;
    const int nb   = (idx >> 5) & 7;
    const int jblk = idx >> 8;
    const int q    = lane & 3;
    const int nr   = lane >> 2;
    const int n    = nb * 8 + nr;
    const int j0   = jblk * 16 + 4 * q;

    float v0 = g_h[(long)(j0 + 0) * F + n];
    float v1 = g_h[(long)(j0 + 1) * F + n];
    float v2 = g_h[(long)(j0 + 2) * F + n];
    float v3 = g_h[(long)(j0 + 3) * F + n];

    g_hB2[idx] = make_uint2(cvt2h(v0, v1), cvt2h(v2, v3));
}

// ---------------- kernel 4: HMMA masked-softmax aggregate ----------------
// 512 CTAs (64 row-blocks x 8 j-splits), 256 threads, no smem/barriers.
// fp16 w x fp16 h (no splits): 1 MMA per n-block per kstep, uint2 B loads.
__global__ __launch_bounds__(256, 2) void hmma_agg_kernel(const int* __restrict__ adj) {
    const int tid  = threadIdx.x;
    const int wid  = tid >> 5;
    const int lane = tid & 31;
    const int q    = lane & 3;
    const int r0   = lane >> 2;
    const int s    = blockIdx.x & (JSPLIT - 1);
    const int i0   = (blockIdx.x >> 3) * 128;
    const int jbase = s * KRANGE;

    const int row0 = i0 + wid * 16 + r0;
    const int row1 = row0 + 8;

    // per-row softmax constants
    const float mx = g_maxe2;
    float t0 = g_e1[row0] + mx, t1 = g_e1[row1] + mx;
    float m0 = fmaxf(t0, ALPHA * t0), m1 = fmaxf(t1, ALPHA * t1);
    const float P0 = __expf(t0 - m0), C0 = __expf(ALPHA * t0 - m0);
    const float P1 = __expf(t1 - m1), C1 = __expf(ALPHA * t1 - m1);

    const int4* a0p = (const int4*)(adj + (long)row0 * NND + jbase) + q;
    const int4* a1p = (const int4*)(adj + (long)row1 * NND + jbase) + q;
    const uint2* bbase = g_hB2 + ((long)(jbase >> 4)) * 256 + lane;

    float acc[8][4];
#pragma unroll
    for (int nb = 0; nb < 8; nb++)
#pragma unroll
        for (int c = 0; c < 4; c++) acc[nb][c] = 0.0f;
    float z0 = 0.0f, z1 = 0.0f;

    int4 av0 = __ldcs(a0p);
    int4 av1 = __ldcs(a1p);

    for (int t = 0; t < KSTEPS; t++) {
        const int4 c0 = av0, c1 = av1;
        if (t + 1 < KSTEPS) {                 // prefetch next kstep's adj
            av0 = __ldcs(a0p + (t + 1) * 4);
            av1 = __ldcs(a1p + (t + 1) * 4);
        }

        const int jq = jbase + t * 16 + 4 * q;
        const float4 f01 = *(const float4*)(g_fBD + jq);      // (Q0,D0,Q1,D1)
        const float4 f23 = *(const float4*)(g_fBD + jq + 2);  // (Q2,D2,Q3,D3)

        float w00 = c0.x ? fmaxf(P0 * f01.x, C0 * f01.y) : 0.0f;
        float w01 = c0.y ? fmaxf(P0 * f01.z, C0 * f01.w) : 0.0f;
        float w02 = c0.z ? fmaxf(P0 * f23.x, C0 * f23.y) : 0.0f;
        float w03 = c0.w ? fmaxf(P0 * f23.z, C0 * f23.w) : 0.0f;
        float w10 = c1.x ? fmaxf(P1 * f01.x, C1 * f01.y) : 0.0f;
        float w11 = c1.y ? fmaxf(P1 * f01.z, C1 * f01.w) : 0.0f;
        float w12 = c1.z ? fmaxf(P1 * f23.x, C1 * f23.y) : 0.0f;
        float w13 = c1.w ? fmaxf(P1 * f23.z, C1 * f23.w) : 0.0f;

        z0 += (w00 + w01) + (w02 + w03);
        z1 += (w10 + w11) + (w12 + w13);

        // A fragments (fp16): a0=(r0,klo) a1=(r1,klo) a2=(r0,khi) a3=(r1,khi)
        u32 a0 = cvt2h(w00, w01), a1 = cvt2h(w10, w11);
        u32 a2 = cvt2h(w02, w03), a3 = cvt2h(w12, w13);

        const uint2* bb = bbase + (long)t * 256;
#pragma unroll
        for (int nb = 0; nb < 8; nb++) {
            uint2 b = __ldg(bb + nb * 32);
            mma_f16(acc[nb], a0, a1, a2, a3, b.x, b.y);   // w * h
        }
    }

    // Z reduce across q (lanes sharing r0)
    z0 += __shfl_xor_sync(0xffffffffu, z0, 1);
    z0 += __shfl_xor_sync(0xffffffffu, z0, 2);
    z1 += __shfl_xor_sync(0xffffffffu, z1, 1);
    z1 += __shfl_xor_sync(0xffffffffu, z1, 2);
    if (q == 0) {
        g_zpart[s * NND + row0] = z0;
        g_zpart[s * NND + row1] = z1;
    }

    // write D partials: d0,d1 -> row0 cols nb*8+2q..+1 ; d2,d3 -> row1
    float* p0 = g_part + ((long)s * NND + row0) * F + 2 * q;
    float* p1 = g_part + ((long)s * NND + row1) * F + 2 * q;
#pragma unroll
    for (int nb = 0; nb < 8; nb++) {
        *(float2*)(p0 + nb * 8) = make_float2(acc[nb][0], acc[nb][1]);
        *(float2*)(p1 + nb * 8) = make_float2(acc[nb][2], acc[nb][3]);
    }
}

// ---------------- kernel 5: combine splits, normalize, ELU (float4) --------
__global__ __launch_bounds__(256) void combine_kernel(float* __restrict__ out) {
    const int t4 = blockIdx.x * 256 + threadIdx.x;   // 0 .. N*F/4-1
    const int i  = t4 >> 4;                          // 16 float4 per row
    float4 acc = make_float4(0.f, 0.f, 0.f, 0.f);
    float  z   = 0.0f;
#pragma unroll
    for (int s = 0; s < JSPLIT; s++) {
        float4 p = __ldcs((const float4*)g_part + (long)s * (NND * F / 4) + t4);
        acc.x += p.x; acc.y += p.y; acc.z += p.z; acc.w += p.w;
        z     += g_zpart[s * NND + i];
    }
    const float zi = 1.0f / z;
    float o0 = acc.x * zi, o1 = acc.y * zi, o2 = acc.z * zi, o3 = acc.w * zi;
    float4 r;
    r.x = (o0 > 0.0f) ? o0 : expm1f(o0);
    r.y = (o1 > 0.0f) ? o1 : expm1f(o1);
    r.z = (o2 > 0.0f) ? o2 : expm1f(o2);
    r.w = (o3 > 0.0f) ? o3 : expm1f(o3);
    *((float4*)out + t4) = r;
}

// ---------------- launch ----------------
extern "C" void kernel_launch(void* const* d_in, const int* in_sizes, int n_in,
                              void* d_out, int out_size) {
    const float* x   = (const float*)d_in[0];
    const int*   adj = (const int*)  d_in[1];
    const float* W   = (const float*)d_in[2];
    const float* a   = (const float*)d_in[3];
    float* out = (float*)d_out;

    gemm_h_kernel<<<NND / 64, 256>>>(x, W);
    e12_kernel<<<NND / 8, 256>>>(a);
    prep_kernel<<<NJBLK, 256>>>();
    hmma_agg_kernel<<<(NND / 128) * JSPLIT, 256>>>(adj);   // 512 CTAs
    combine_kernel<<<(NND * F) / 1024, 256>>>(out);
}

// round 17
// speedup vs baseline: 2.4170x; 1.1149x over previous
#include <cuda_runtime.h>
#include <cuda_fp16.h>
#include <math.h>
#include <stdint.h>

#define NND    8192
#define IN_F   512
#define F      64
#define ALPHA  0.2f

#define JSPLIT 8
#define KRANGE (NND / JSPLIT)      // 1024 j per CTA
#define KSTEPS (KRANGE / 16)       // 64
#define NJBLK  (NND / 16)          // 512

typedef unsigned long long ull;
typedef unsigned int u32;

// ---------------- device scratch ----------------
__device__ float  g_h[NND * F];                    // 2 MB
__device__ float  g_e1[NND];
__device__ float  g_e2[NND];
__device__ float  g_maxe2;
__device__ float2 g_fBD[NND];                      // per-j (Q_j, D_j)
__device__ uint2  g_hB2[NJBLK * 8 * 32];           // B frags {b0h,b1h} fp16, 1 MB
__device__ float  g_part[(long)JSPLIT * NND * F];  // 16 MB partials
__device__ float  g_zpart[JSPLIT * NND];

// ---------------- helpers ----------------
__device__ __forceinline__ ull pack2(float x, float y) {
    ull r; asm("mov.b64 %0, {%1, %2};" : "=l"(r) : "f"(x), "f"(y)); return r;
}
__device__ __forceinline__ void ffma2(ull &d, ull a, ull b) {
    asm("fma.rn.f32x2 %0, %1, %2, %3;" : "=l"(d) : "l"(a), "l"(b), "l"(d));
}
__device__ __forceinline__ float2 unpack2(ull v) {
    float2 r; asm("mov.b64 {%0, %1}, %2;" : "=f"(r.x), "=f"(r.y) : "l"(v)); return r;
}
// pack fp16x2: lo -> low half (even k), hi -> high half (odd k)
__device__ __forceinline__ u32 cvt2h(float lo, float hi) {
    u32 r; asm("cvt.rn.f16x2.f32 %0, %1, %2;" : "=r"(r) : "f"(hi), "f"(lo)); return r;
}

// m16n8k16 fp16 MMA, f32 accumulate (base PTX, valid for compute_103)
__device__ __forceinline__ void mma_f16(float* d,
                                        u32 a0, u32 a1, u32 a2, u32 a3,
                                        u32 b0, u32 b1) {
    asm volatile(
        "mma.sync.aligned.m16n8k16.row.col.f32.f16.f16.f32 "
        "{%0,%1,%2,%3}, {%4,%5,%6,%7}, {%8,%9}, {%0,%1,%2,%3};"
        : "+f"(d[0]), "+f"(d[1]), "+f"(d[2]), "+f"(d[3])
        : "r"(a0), "r"(a1), "r"(a2), "r"(a3), "r"(b0), "r"(b1));
}

// ---------------- kernel 1: h = x @ W (fp32 f32x2 SIMT) ----------------
__global__ __launch_bounds__(256) void gemm_h_kernel(const float* __restrict__ x,
                                                     const float* __restrict__ W) {
    __shared__ float xs[64 * 68];
    __shared__ float wsm[64 * 64];

    const int tid = threadIdx.x;
    const int i0  = blockIdx.x * 64;
    const int tf  = tid & 15;
    const int tg  = tid >> 4;

    ull acc[4][2];
#pragma unroll
    for (int r = 0; r < 4; r++) { acc[r][0] = 0ull; acc[r][1] = 0ull; }

    for (int kt = 0; kt < IN_F; kt += 64) {
#pragma unroll
        for (int q = tid; q < 1024; q += 256) {
            int row = q >> 4, c4 = q & 15;
            float4 v = *(const float4*)(x + (long)(i0 + row) * IN_F + kt + c4 * 4);
            *(float4*)(xs + row * 68 + c4 * 4) = v;
        }
#pragma unroll
        for (int q = tid; q < 1024; q += 256) {
            float4 v = *(const float4*)(W + (long)kt * F + q * 4);
            *(float4*)(wsm + q * 4) = v;
        }
        __syncthreads();
#pragma unroll 8
        for (int kk = 0; kk < 64; kk++) {
            ulonglong2 wp = *(const ulonglong2*)(wsm + kk * 64 + tf * 4);
#pragma unroll
            for (int r = 0; r < 4; r++) {
                float xv = xs[(tg * 4 + r) * 68 + kk];
                ull x2 = pack2(xv, xv);
                ffma2(acc[r][0], x2, wp.x);
                ffma2(acc[r][1], x2, wp.y);
            }
        }
        __syncthreads();
    }
#pragma unroll
    for (int r = 0; r < 4; r++) {
        float2 lo = unpack2(acc[r][0]);
        float2 hi = unpack2(acc[r][1]);
        *(float4*)(g_h + (long)(i0 + tg * 4 + r) * F + tf * 4) =
            make_float4(lo.x, lo.y, hi.x, hi.y);
    }
}

// ---------------- kernel 2: e1 = h@a1, e2 = h@a2 (warp per row) ----------------
__global__ __launch_bounds__(256) void e12_kernel(const float* __restrict__ a) {
    const int tid  = threadIdx.x;
    const int lane = tid & 31;
    const int row  = blockIdx.x * 8 + (tid >> 5);

    float h0 = g_h[row * F + 2 * lane];
    float h1 = g_h[row * F + 2 * lane + 1];
    float p1 = h0 * a[2 * lane]      + h1 * a[2 * lane + 1];
    float p2 = h0 * a[64 + 2 * lane] + h1 * a[64 + 2 * lane + 1];
#pragma unroll
    for (int off = 16; off > 0; off >>= 1) {
        p1 += __shfl_xor_sync(0xffffffffu, p1, off);
        p2 += __shfl_xor_sync(0xffffffffu, p2, off);
    }
    if (lane == 0) { g_e1[row] = p1; g_e2[row] = p2; }
}

// ---- kernel 3: prep = max(e2) (redundant/block) + fbd (blocks 0-31) + hfrag
__global__ __launch_bounds__(256) void prep_kernel() {
    __shared__ float sm[8];
    const int tid = threadIdx.x;

    // redundant global max of e2 (L2-hot)
    float v = -3.4e38f;
#pragma unroll
    for (int k = 0; k < NND / 256; k++) v = fmaxf(v, g_e2[k * 256 + tid]);
#pragma unroll
    for (int off = 16; off > 0; off >>= 1)
        v = fmaxf(v, __shfl_xor_sync(0xffffffffu, v, off));
    if ((tid & 31) == 0) sm[tid >> 5] = v;
    __syncthreads();
    const float mx = fmaxf(fmaxf(fmaxf(sm[0], sm[1]), fmaxf(sm[2], sm[3])),
                           fmaxf(fmaxf(sm[4], sm[5]), fmaxf(sm[6], sm[7])));

    if (blockIdx.x == 0 && tid == 0) g_maxe2 = mx;

    // fbd: blocks 0..31 cover all 8192 j
    if (blockIdx.x < 32) {
        const int j = blockIdx.x * 256 + tid;
        const float d = g_e2[j] - mx;
        g_fBD[j] = make_float2(__expf(d), __expf(ALPHA * d));
    }

    // hfrag: idx = jblk*256 + nb*32 + lane  (fp16 B fragments, no split)
    const int idx  = blockIdx.x * 256 + tid;
    const int lane = idx & 31;
    const int nb   = (idx >> 5) & 7;
    const int jblk = idx >> 8;
    const int q    = lane & 3;
    const int nr   = lane >> 2;
    const int n    = nb * 8 + nr;
    const int j0   = jblk * 16 + 4 * q;

    float v0 = g_h[(long)(j0 + 0) * F + n];
    float v1 = g_h[(long)(j0 + 1) * F + n];
    float v2 = g_h[(long)(j0 + 2) * F + n];
    float v3 = g_h[(long)(j0 + 3) * F + n];

    g_hB2[idx] = make_uint2(cvt2h(v0, v1), cvt2h(v2, v3));
}

// ---------------- kernel 4: HMMA masked-softmax aggregate ----------------
// 512 CTAs (64 row-blocks x 8 j-splits), 256 threads, no smem/barriers.
// fp16 w x fp16 h: 1 MMA per n-block per kstep, uint2 B loads. THIS ROUND:
// fac (Q,D) prefetched one kstep ahead (8 regs of slack now exist under cap).
__global__ __launch_bounds__(256, 2) void hmma_agg_kernel(const int* __restrict__ adj) {
    const int tid  = threadIdx.x;
    const int wid  = tid >> 5;
    const int lane = tid & 31;
    const int q    = lane & 3;
    const int r0   = lane >> 2;
    const int s    = blockIdx.x & (JSPLIT - 1);
    const int i0   = (blockIdx.x >> 3) * 128;
    const int jbase = s * KRANGE;

    const int row0 = i0 + wid * 16 + r0;
    const int row1 = row0 + 8;

    // per-row softmax constants
    const float mx = g_maxe2;
    float t0 = g_e1[row0] + mx, t1 = g_e1[row1] + mx;
    float m0 = fmaxf(t0, ALPHA * t0), m1 = fmaxf(t1, ALPHA * t1);
    const float P0 = __expf(t0 - m0), C0 = __expf(ALPHA * t0 - m0);
    const float P1 = __expf(t1 - m1), C1 = __expf(ALPHA * t1 - m1);

    const int4* a0p = (const int4*)(adj + (long)row0 * NND + jbase) + q;
    const int4* a1p = (const int4*)(adj + (long)row1 * NND + jbase) + q;
    const uint2* bbase = g_hB2 + ((long)(jbase >> 4)) * 256 + lane;
    // fac pointer: lane q covers j = t*16 + 4q..4q+3 -> float4 idx 2q,
    // kstep stride = 16 float2 = 8 float4
    const float4* fp = (const float4*)(g_fBD + jbase) + 2 * q;

    float acc[8][4];
#pragma unroll
    for (int nb = 0; nb < 8; nb++)
#pragma unroll
        for (int c = 0; c < 4; c++) acc[nb][c] = 0.0f;
    float z0 = 0.0f, z1 = 0.0f;

    int4 av0 = __ldcs(a0p);
    int4 av1 = __ldcs(a1p);
    float4 ff0 = __ldg(fp);
    float4 ff1 = __ldg(fp + 1);

    for (int t = 0; t < KSTEPS; t++) {
        const int4   c0  = av0, c1 = av1;
        const float4 f01 = ff0, f23 = ff1;
        if (t + 1 < KSTEPS) {                 // prefetch next kstep's adj + fac
            av0 = __ldcs(a0p + (t + 1) * 4);
            av1 = __ldcs(a1p + (t + 1) * 4);
            ff0 = __ldg(fp + (t + 1) * 8);
            ff1 = __ldg(fp + (t + 1) * 8 + 1);
        }

        float w00 = c0.x ? fmaxf(P0 * f01.x, C0 * f01.y) : 0.0f;
        float w01 = c0.y ? fmaxf(P0 * f01.z, C0 * f01.w) : 0.0f;
        float w02 = c0.z ? fmaxf(P0 * f23.x, C0 * f23.y) : 0.0f;
        float w03 = c0.w ? fmaxf(P0 * f23.z, C0 * f23.w) : 0.0f;
        float w10 = c1.x ? fmaxf(P1 * f01.x, C1 * f01.y) : 0.0f;
        float w11 = c1.y ? fmaxf(P1 * f01.z, C1 * f01.w) : 0.0f;
        float w12 = c1.z ? fmaxf(P1 * f23.x, C1 * f23.y) : 0.0f;
        float w13 = c1.w ? fmaxf(P1 * f23.z, C1 * f23.w) : 0.0f;

        z0 += (w00 + w01) + (w02 + w03);
        z1 += (w10 + w11) + (w12 + w13);

        // A fragments (fp16): a0=(r0,klo) a1=(r1,klo) a2=(r0,khi) a3=(r1,khi)
        u32 a0 = cvt2h(w00, w01), a1 = cvt2h(w10, w11);
        u32 a2 = cvt2h(w02, w03), a3 = cvt2h(w12, w13);

        const uint2* bb = bbase + (long)t * 256;
#pragma unroll
        for (int nb = 0; nb < 8; nb++) {
            uint2 b = __ldg(bb + nb * 32);
            mma_f16(acc[nb], a0, a1, a2, a3, b.x, b.y);   // w * h
        }
    }

    // Z reduce across q (lanes sharing r0)
    z0 += __shfl_xor_sync(0xffffffffu, z0, 1);
    z0 += __shfl_xor_sync(0xffffffffu, z0, 2);
    z1 += __shfl_xor_sync(0xffffffffu, z1, 1);
    z1 += __shfl_xor_sync(0xffffffffu, z1, 2);
    if (q == 0) {
        g_zpart[s * NND + row0] = z0;
        g_zpart[s * NND + row1] = z1;
    }

    // write D partials: d0,d1 -> row0 cols nb*8+2q..+1 ; d2,d3 -> row1
    float* p0 = g_part + ((long)s * NND + row0) * F + 2 * q;
    float* p1 = g_part + ((long)s * NND + row1) * F + 2 * q;
#pragma unroll
    for (int nb = 0; nb < 8; nb++) {
        *(float2*)(p0 + nb * 8) = make_float2(acc[nb][0], acc[nb][1]);
        *(float2*)(p1 + nb * 8) = make_float2(acc[nb][2], acc[nb][3]);
    }
}

// ---------------- kernel 5: combine splits, normalize, ELU (float4) --------
__global__ __launch_bounds__(256) void combine_kernel(float* __restrict__ out) {
    const int t4 = blockIdx.x * 256 + threadIdx.x;   // 0 .. N*F/4-1
    const int i  = t4 >> 4;                          // 16 float4 per row
    float4 acc = make_float4(0.f, 0.f, 0.f, 0.f);
    float  z   = 0.0f;
#pragma unroll
    for (int s = 0; s < JSPLIT; s++) {
        float4 p = __ldcs((const float4*)g_part + (long)s * (NND * F / 4) + t4);
        acc.x += p.x; acc.y += p.y; acc.z += p.z; acc.w += p.w;
        z     += g_zpart[s * NND + i];
    }
    const float zi = 1.0f / z;
    float o0 = acc.x * zi, o1 = acc.y * zi, o2 = acc.z * zi, o3 = acc.w * zi;
    float4 r;
    r.x = (o0 > 0.0f) ? o0 : expm1f(o0);
    r.y = (o1 > 0.0f) ? o1 : expm1f(o1);
    r.z = (o2 > 0.0f) ? o2 : expm1f(o2);
    r.w = (o3 > 0.0f) ? o3 : expm1f(o3);
    *((float4*)out + t4) = r;
}

// ---------------- launch ----------------
extern "C" void kernel_launch(void* const* d_in, const int* in_sizes, int n_in,
                              void* d_out, int out_size) {
    const float* x   = (const float*)d_in[0];
    const int*   adj = (const int*)  d_in[1];
    const float* W   = (const float*)d_in[2];
    const float* a   = (const float*)d_in[3];
    float* out = (float*)d_out;

    gemm_h_kernel<<<NND / 64, 256>>>(x, W);
    e12_kernel<<<NND / 8, 256>>>(a);
    prep_kernel<<<NJBLK, 256>>>();
    hmma_agg_kernel<<<(NND / 128) * JSPLIT, 256>>>(adj);   // 512 CTAs
    combine_kernel<<<(NND * F) / 1024, 256>>>(out);
}